// round 13
// baseline (speedup 1.0000x reference)
#include <cuda_runtime.h>
#include <cuda_bf16.h>
#include <cstdint>

// Intermediate: h1 after conv1+bn+relu+pool : [8,48,48,48,8] floats = 28.3 MB
__device__ float g_h1[8 * 48 * 48 * 48 * 8];

#define BN_EPS 1e-5f

// ---- tf32 mma helpers -------------------------------------------------------
__device__ __forceinline__ uint32_t f2tf32(float f) {
    uint32_t r;
    asm("cvt.rna.tf32.f32 %0, %1;" : "=r"(r) : "f"(f));
    return r;
}
__device__ __forceinline__ void mma_tf32_r(float* d, uint32_t a0, uint32_t a1,
                                           uint32_t a2, uint32_t a3,
                                           uint32_t b0, uint32_t b1) {
    asm volatile(
        "mma.sync.aligned.m16n8k8.row.col.f32.tf32.tf32.f32 "
        "{%0,%1,%2,%3}, {%4,%5,%6,%7}, {%8,%9}, {%0,%1,%2,%3};"
        : "+f"(d[0]), "+f"(d[1]), "+f"(d[2]), "+f"(d[3])
        : "r"(a0), "r"(a1), "r"(a2), "r"(a3), "r"(b0), "r"(b1));
}

// ---------------------------------------------------------------------------
// Kernel A (mma.sync tf32): conv1 (3x3x3, 1->8) + BN + ReLU + maxpool2
// Block = 128 conv positions (8x x 4y x 4z), 128 threads, warp w <-> pz = w.
// GEMM [128 pos] x [K=27 pad 32] x [8 co]. Halo (single channel, 10x6x6)
// stored tf32-rounded; B entirely in registers (8 vals/thread, loaded once).
// Taps 27..31: B = 0 (A reads clamped to tap 26, finite x 0 = 0).
// ---------------------------------------------------------------------------
__global__ void __launch_bounds__(128, 8) conv1_mma_kernel(
    const float* __restrict__ x,   // [8,96,96,96,1]
    const float* __restrict__ W1,  // [3,3,3,1,8] -> [tap][co], 216
    const float* __restrict__ b1, const float* __restrict__ g1,
    const float* __restrict__ be1, const float* __restrict__ m1,
    const float* __restrict__ v1)
{
    __shared__ uint32_t s_halo[360];     // [z6][y6][x10], tf32 bits
    __shared__ float s_w[216];           // BN-folded [tap][co]
    __shared__ float s_beta[8];
    __shared__ float s_pool[128 * 9];    // [pos][co] stride 9

    const int b  = blockIdx.y;
    const int t  = blockIdx.x;           // 0..6911 = 12(x)*24(y)*24(z)
    const int tx = t % 12, ty = (t / 12) % 24, tz = t / 288;
    const int X0 = tx * 8, Y0 = ty * 4, Z0 = tz * 4;   // conv-tile origin
    const int tid = threadIdx.x;
    const int wid = tid >> 5, lane = tid & 31;

    // halo: 10x * 6y * 6z around the conv tile, zero-padded, tf32-rounded
    for (int i = tid; i < 360; i += 128) {
        int x10 = i % 10, yz = i / 10;
        int y6 = yz % 6, z6 = yz / 6;
        int gz = Z0 - 1 + z6, gy = Y0 - 1 + y6, gx = X0 - 1 + x10;
        float v = 0.f;
        if ((unsigned)gz < 96u && (unsigned)gy < 96u && (unsigned)gx < 96u)
            v = x[((b * 96 + gz) * 96 + gy) * 96 + gx];
        s_halo[z6 * 60 + y6 * 10 + x10] = f2tf32(v);
    }
    // BUGFIX (R11): 128-thread block -> strided loop, not `if (tid < 216)`;
    // taps 16..26 were previously uninitialized.
    for (int i = tid; i < 216; i += 128) {
        int c = i & 7;
        float s = g1[c] * rsqrtf(v1[c] + BN_EPS);
        s_w[i] = W1[i] * s;
    }
    if (tid < 8) {
        float s = g1[tid] * rsqrtf(v1[tid] + BN_EPS);
        s_beta[tid] = (b1[tid] - m1[tid]) * s + be1[tid];
    }
    __syncthreads();

    const int r_lo = lane >> 2;          // px (m-row) / co (n-col)
    const int ci   = lane & 3;           // k within 8
    const uint32_t* hbase = s_halo + wid * 60 + r_lo;   // + py*10 + tap-offset

    // per-thread tap offsets + B fragments (once, outside the loop)
    int aoffk[4][2];
    uint32_t bk[4][2];
    #pragma unroll
    for (int ks = 0; ks < 4; ks++) {
        #pragma unroll
        for (int par = 0; par < 2; par++) {
            int tap = ks * 8 + ci + 4 * par;
            int tc = tap < 27 ? tap : 26;
            aoffk[ks][par] = (tc / 9) * 60 + ((tc / 3) % 3) * 10 + (tc % 3);
            bk[ks][par] = (tap < 27) ? f2tf32(s_w[tap * 8 + r_lo]) : 0u;
        }
    }

    float d0[4] = {0.f, 0.f, 0.f, 0.f};  // m-chunk h=0 (py 0,1)
    float d1[4] = {0.f, 0.f, 0.f, 0.f};  // m-chunk h=1 (py 2,3)

    #pragma unroll
    for (int ks = 0; ks < 4; ks++) {
        const int oA = aoffk[ks][0], oB = aoffk[ks][1];
        const uint32_t ba = bk[ks][0], bb = bk[ks][1];
        // h=0: rows = py 0 (a0/a2), py 1 (a1/a3)
        mma_tf32_r(d0, hbase[oA], hbase[oA + 10], hbase[oB], hbase[oB + 10],
                   ba, bb);
        // h=1: py 2, py 3
        mma_tf32_r(d1, hbase[oA + 20], hbase[oA + 30], hbase[oB + 20],
                   hbase[oB + 30], ba, bb);
    }

    // scatter D to s_pool: pos p = wid*32 + h*16 + r_lo + 8*(reg>=2), co = 2ci+(reg&1)
    {
        const int p00 = wid * 32 + r_lo;          // h=0, rows r_lo / r_lo+8
        const int p10 = wid * 32 + 16 + r_lo;     // h=1
        const int co = 2 * ci;
        s_pool[p00 * 9 + co]           = d0[0];
        s_pool[p00 * 9 + co + 1]       = d0[1];
        s_pool[(p00 + 8) * 9 + co]     = d0[2];
        s_pool[(p00 + 8) * 9 + co + 1] = d0[3];
        s_pool[p10 * 9 + co]           = d1[0];
        s_pool[p10 * 9 + co + 1]       = d1[1];
        s_pool[(p10 + 8) * 9 + co]     = d1[2];
        s_pool[(p10 + 8) * 9 + co + 1] = d1[3];
    }
    __syncthreads();

    // maxpool 2x2x2 + bias + relu: thread = (voxel, channel)
    {
        const int v = tid >> 3, ch = tid & 7;
        const int qx = v & 3, qy = (v >> 2) & 1, qz = v >> 3;
        float m = -3.4e38f;
        #pragma unroll
        for (int p = 0; p < 8; p++) {
            const int dz = p >> 2, dy = (p >> 1) & 1, dx = p & 1;
            const int pos = (2 * qz + dz) * 32 + (2 * qy + dy) * 8 + (2 * qx + dx);
            m = fmaxf(m, s_pool[pos * 9 + ch]);
        }
        m = fmaxf(m + s_beta[ch], 0.f);
        const int gz = tz * 2 + qz, gy = ty * 2 + qy, gx = tx * 4 + qx;
        g_h1[(((b * 48 + gz) * 48 + gy) * 48 + gx) * 8 + ch] = m;
    }
}

// ---------------------------------------------------------------------------
// Kernel B (mma.sync tf32, LDS.64 paired): conv2 + BN + ReLU + maxpool2 + FC
// (unchanged from the measured 75.7us version)
// ---------------------------------------------------------------------------
__global__ void __launch_bounds__(128, 6) conv2_mma_kernel(
    const float* __restrict__ W2,  // [3,3,3,8,16] -> [tap][ci][co]
    const float* __restrict__ b2, const float* __restrict__ g2,
    const float* __restrict__ be2, const float* __restrict__ m2,
    const float* __restrict__ v2,
    const float* __restrict__ Wf,  // [16,5]
    const float* __restrict__ bf,  // [5]
    float* __restrict__ out)       // [8,24,24,24,5]
{
    __shared__ __align__(16) uint32_t s_in[6 * 6 * 80];   // tf32 halo (reused as pool buf)
    __shared__ __align__(16) uint32_t s_wB[27 * 128];     // tf32 weights [tap][co][ci-int]
    __shared__ float s_wf[80], s_beta[16], s_bf[5];

    const int b  = blockIdx.y;
    const int t  = blockIdx.x;                    // 0..863 = 6(x)*12(y)*12(z)
    const int tx = t % 6, ty = (t / 6) % 12, tz = t / 72;
    const int Z0 = tz * 4, Y0 = ty * 4, X0 = tx * 8;
    const int tid = threadIdx.x;
    const int wid = tid >> 5, lane = tid & 31;

    if (tid < 16) {
        float s = g2[tid] * rsqrtf(v2[tid] + BN_EPS);
        s_beta[tid] = (b2[tid] - m2[tid]) * s + be2[tid];
    }
    if (tid < 80) s_wf[tid] = Wf[tid];
    if (tid < 5)  s_bf[tid] = bf[tid];

    // Weights: s_wB[tap*128 + co*8 + slot] ; slot = (ci%4)*2 + ci/4
    for (int i = tid; i < 3456; i += 128) {
        int tap = i >> 7, co = (i >> 3) & 15, slot = i & 7;
        int ci = (slot >> 1) + (slot & 1) * 4;
        float s = g2[co] * rsqrtf(v2[co] + BN_EPS);
        s_wB[i] = f2tf32(W2[tap * 128 + ci * 16 + co] * s);
    }

    // Halo: 360 voxels, tf32 + channel interleave (c0,c4,c1,c5,c2,c6,c3,c7)
    for (int j = tid; j < 360; j += 128) {
        int x10 = j % 10, yz = j / 10;
        int y6 = yz % 6, z6 = yz / 6;
        int gz = Z0 - 1 + z6, gy = Y0 - 1 + y6, gx = X0 - 1 + x10;
        float4 a = make_float4(0.f, 0.f, 0.f, 0.f), c = a;
        if ((unsigned)gz < 48u && (unsigned)gy < 48u && (unsigned)gx < 48u) {
            const float* p = &g_h1[(((b * 48 + gz) * 48 + gy) * 48 + gx) * 8];
            a = *(const float4*)p;
            c = *(const float4*)(p + 4);
        }
        uint32_t* d = &s_in[(z6 * 6 + y6) * 80 + x10 * 8];
        ((uint4*)d)[0] = make_uint4(f2tf32(a.x), f2tf32(c.x), f2tf32(a.y), f2tf32(c.y));
        ((uint4*)d)[1] = make_uint4(f2tf32(a.z), f2tf32(c.z), f2tf32(a.w), f2tf32(c.w));
    }
    __syncthreads();

    const int r_lo = lane >> 2;
    const int ci_lo = lane & 3;
    const int pz = wid;

    const uint2* aBase0 = (const uint2*)&s_in[(pz * 6 + 0) * 80 + r_lo * 8 + 2 * ci_lo];
    const uint2* aBase1 = (const uint2*)&s_in[(pz * 6 + 2) * 80 + r_lo * 8 + 2 * ci_lo];
    const uint2* bBase  = (const uint2*)&s_wB[r_lo * 8 + 2 * ci_lo];

    float d[2][2][4];
    #pragma unroll
    for (int h = 0; h < 2; h++)
        #pragma unroll
        for (int n = 0; n < 2; n++)
            #pragma unroll
            for (int k = 0; k < 4; k++) d[h][n][k] = 0.f;

    #pragma unroll
    for (int tap = 0; tap < 27; tap++) {
        const int dz = tap / 9, dy = (tap / 3) % 3, dx = tap % 3;
        const int aoff = (dz * 480 + dy * 80 + dx * 8) >> 1;
        const uint2 bA = bBase[tap * 64];
        const uint2 bB = bBase[tap * 64 + 32];
        const uint2 l00 = aBase0[aoff];
        const uint2 l01 = aBase0[aoff + 40];
        const uint2 l10 = aBase1[aoff];
        const uint2 l11 = aBase1[aoff + 40];

        mma_tf32_r(d[0][0], l00.x, l01.x, l00.y, l01.y, bA.x, bA.y);
        mma_tf32_r(d[0][1], l00.x, l01.x, l00.y, l01.y, bB.x, bB.y);
        mma_tf32_r(d[1][0], l10.x, l11.x, l10.y, l11.y, bA.x, bA.y);
        mma_tf32_r(d[1][1], l10.x, l11.x, l10.y, l11.y, bB.x, bB.y);
    }

    __syncthreads();
    float* s_pool = (float*)s_in;        // [128 pos][16 co], stride 17
    #pragma unroll
    for (int h = 0; h < 2; h++) {
        const int pos0 = pz * 32 + (h * 2) * 8 + r_lo;
        const int pos1 = pos0 + 8;
        #pragma unroll
        for (int nb = 0; nb < 2; nb++) {
            const int co = nb * 8 + 2 * ci_lo;
            s_pool[pos0 * 17 + co]     = d[h][nb][0];
            s_pool[pos0 * 17 + co + 1] = d[h][nb][1];
            s_pool[pos1 * 17 + co]     = d[h][nb][2];
            s_pool[pos1 * 17 + co + 1] = d[h][nb][3];
        }
    }
    __syncthreads();

    if (tid < 16) {
        const int qx = tid & 3, qy = (tid >> 2) & 1, qz = tid >> 3;
        float mx[16];
        #pragma unroll
        for (int c = 0; c < 16; c++) mx[c] = -3.4e38f;
        #pragma unroll
        for (int p = 0; p < 8; p++) {
            const int ddz = p >> 2, ddy = (p >> 1) & 1, ddx = p & 1;
            const int m = (2 * qz + ddz) * 32 + (2 * qy + ddy) * 8 + (2 * qx + ddx);
            #pragma unroll
            for (int c = 0; c < 16; c++)
                mx[c] = fmaxf(mx[c], s_pool[m * 17 + c]);
        }
        #pragma unroll
        for (int c = 0; c < 16; c++) mx[c] = fmaxf(mx[c] + s_beta[c], 0.f);
        const int gz = tz * 2 + qz, gy = ty * 2 + qy, gx = tx * 4 + qx;
        float* op = &out[(((b * 24 + gz) * 24 + gy) * 24 + gx) * 5];
        #pragma unroll
        for (int n = 0; n < 5; n++) {
            float o = s_bf[n];
            #pragma unroll
            for (int c = 0; c < 16; c++) o += mx[c] * s_wf[c * 5 + n];
            op[n] = o;
        }
    }
}

// ---------------------------------------------------------------------------
extern "C" void kernel_launch(void* const* d_in, const int* in_sizes, int n_in,
                              void* d_out, int out_size) {
    const float* x   = (const float*)d_in[0];
    const float* W1  = (const float*)d_in[1];
    const float* b1  = (const float*)d_in[2];
    const float* g1  = (const float*)d_in[3];
    const float* be1 = (const float*)d_in[4];
    const float* m1  = (const float*)d_in[5];
    const float* v1  = (const float*)d_in[6];
    const float* W2  = (const float*)d_in[7];
    const float* b2  = (const float*)d_in[8];
    const float* g2  = (const float*)d_in[9];
    const float* be2 = (const float*)d_in[10];
    const float* m2  = (const float*)d_in[11];
    const float* v2  = (const float*)d_in[12];
    const float* Wf  = (const float*)d_in[13];
    const float* bf  = (const float*)d_in[14];
    float* out = (float*)d_out;

    dim3 gridA(6912, 8);   // 12x * 24y * 24z conv tiles
    conv1_mma_kernel<<<gridA, 128>>>(x, W1, b1, g1, be1, m1, v1);

    dim3 gridB(864, 8);
    conv2_mma_kernel<<<gridB, 128>>>(W2, b2, g2, be2, m2, v2, Wf, bf, out);
}

// round 15
// speedup vs baseline: 1.0331x; 1.0331x over previous
#include <cuda_runtime.h>
#include <cuda_bf16.h>
#include <cstdint>

// Intermediate: h1 after conv1+bn+relu+pool : [8,48,48,48,8] floats = 28.3 MB
__device__ float g_h1[8 * 48 * 48 * 48 * 8];

#define BN_EPS 1e-5f

// ---- tf32 mma helpers -------------------------------------------------------
__device__ __forceinline__ uint32_t f2tf32(float f) {
    uint32_t r;
    asm("cvt.rna.tf32.f32 %0, %1;" : "=r"(r) : "f"(f));
    return r;
}
__device__ __forceinline__ void mma_tf32_r(float* d, uint32_t a0, uint32_t a1,
                                           uint32_t a2, uint32_t a3,
                                           uint32_t b0, uint32_t b1) {
    asm volatile(
        "mma.sync.aligned.m16n8k8.row.col.f32.tf32.tf32.f32 "
        "{%0,%1,%2,%3}, {%4,%5,%6,%7}, {%8,%9}, {%0,%1,%2,%3};"
        : "+f"(d[0]), "+f"(d[1]), "+f"(d[2]), "+f"(d[3])
        : "r"(a0), "r"(a1), "r"(a2), "r"(a3), "r"(b0), "r"(b1));
}

// ---------------------------------------------------------------------------
// Kernel A (mma.sync tf32): conv1 (3x3x3, 1->8) + BN + ReLU + maxpool2
// Block = 512 conv positions (8x x 8y x 8z), 512 threads = 16 warps.
// Warp w: pz = w>>1, py_base = (w&1)*4 -> 32 positions (2 m-chunks of m16).
// GEMM [512 pos] x [K=27 pad 32] x [8 co]. Halo 10x10x10 single channel,
// tf32-rounded in smem; B in registers (8 vals/thread). Taps 27..31: B=0.
// ---------------------------------------------------------------------------
__global__ void __launch_bounds__(512, 3) conv1_mma_kernel(
    const float* __restrict__ x,   // [8,96,96,96,1]
    const float* __restrict__ W1,  // [3,3,3,1,8] -> [tap][co], 216
    const float* __restrict__ b1, const float* __restrict__ g1,
    const float* __restrict__ be1, const float* __restrict__ m1,
    const float* __restrict__ v1)
{
    __shared__ uint32_t s_halo[1000];    // [z10][y10][x10], tf32 bits, 4 KB
    __shared__ float s_w[216];           // BN-folded [tap][co]
    __shared__ float s_beta[8];
    __shared__ float s_pool[512 * 9];    // [pos][co] stride 9, 18.4 KB

    const int b  = blockIdx.y;
    const int t  = blockIdx.x;           // 0..1727 = 12(x)*12(y)*12(z)
    const int tx = t % 12, ty = (t / 12) % 12, tz = t / 144;
    const int X0 = tx * 8, Y0 = ty * 8, Z0 = tz * 8;   // conv-tile origin
    const int tid = threadIdx.x;
    const int wid = tid >> 5, lane = tid & 31;

    // halo: 10^3 around the conv tile, zero-padded, tf32-rounded
    for (int i = tid; i < 1000; i += 512) {
        int x10 = i % 10, y10 = (i / 10) % 10, z10 = i / 100;
        int gz = Z0 - 1 + z10, gy = Y0 - 1 + y10, gx = X0 - 1 + x10;
        float v = 0.f;
        if ((unsigned)gz < 96u && (unsigned)gy < 96u && (unsigned)gx < 96u)
            v = x[((b * 96 + gz) * 96 + gy) * 96 + gx];
        s_halo[z10 * 100 + y10 * 10 + x10] = f2tf32(v);
    }
    // weight fold (512 threads: single strided pass covers all 216)
    for (int i = tid; i < 216; i += 512) {
        int c = i & 7;
        float s = g1[c] * rsqrtf(v1[c] + BN_EPS);
        s_w[i] = W1[i] * s;
    }
    if (tid < 8) {
        float s = g1[tid] * rsqrtf(v1[tid] + BN_EPS);
        s_beta[tid] = (b1[tid] - m1[tid]) * s + be1[tid];
    }
    __syncthreads();

    const int r_lo = lane >> 2;          // px (m-row) / co (n-col)
    const int ci   = lane & 3;           // k within 8
    const int pz   = wid >> 1;
    const int pyb  = (wid & 1) * 4;
    const uint32_t* hbase = s_halo + pz * 100 + pyb * 10 + r_lo;

    // per-thread tap offsets + B fragments (loaded once)
    int aoffk[4][2];
    uint32_t bk[4][2];
    #pragma unroll
    for (int ks = 0; ks < 4; ks++) {
        #pragma unroll
        for (int par = 0; par < 2; par++) {
            int tap = ks * 8 + ci + 4 * par;
            int tc = tap < 27 ? tap : 26;
            aoffk[ks][par] = (tc / 9) * 100 + ((tc / 3) % 3) * 10 + (tc % 3);
            bk[ks][par] = (tap < 27) ? f2tf32(s_w[tap * 8 + r_lo]) : 0u;
        }
    }

    float d0[4] = {0.f, 0.f, 0.f, 0.f};  // m-chunk h=0 (py pyb+0,1)
    float d1[4] = {0.f, 0.f, 0.f, 0.f};  // m-chunk h=1 (py pyb+2,3)

    #pragma unroll
    for (int ks = 0; ks < 4; ks++) {
        const int oA = aoffk[ks][0], oB = aoffk[ks][1];
        const uint32_t ba = bk[ks][0], bb = bk[ks][1];
        mma_tf32_r(d0, hbase[oA], hbase[oA + 10], hbase[oB], hbase[oB + 10],
                   ba, bb);
        mma_tf32_r(d1, hbase[oA + 20], hbase[oA + 30], hbase[oB + 20],
                   hbase[oB + 30], ba, bb);
    }

    // scatter D: pos = pz*64 + py*8 + px
    {
        const int p00 = pz * 64 + pyb * 8 + r_lo;   // py = pyb
        const int p10 = p00 + 16;                   // py = pyb+2
        const int co = 2 * ci;
        s_pool[p00 * 9 + co]           = d0[0];
        s_pool[p00 * 9 + co + 1]       = d0[1];
        s_pool[(p00 + 8) * 9 + co]     = d0[2];     // py = pyb+1
        s_pool[(p00 + 8) * 9 + co + 1] = d0[3];
        s_pool[p10 * 9 + co]           = d1[0];
        s_pool[p10 * 9 + co + 1]       = d1[1];
        s_pool[(p10 + 8) * 9 + co]     = d1[2];     // py = pyb+3
        s_pool[(p10 + 8) * 9 + co + 1] = d1[3];
    }
    __syncthreads();

    // maxpool 2x2x2 + bias + relu: thread = (voxel, channel); 64 vox x 8 ch
    {
        const int v = tid >> 3, ch = tid & 7;
        const int qx = v & 3, qy = (v >> 2) & 3, qz = (v >> 4) & 3;
        float m = -3.4e38f;
        #pragma unroll
        for (int p = 0; p < 8; p++) {
            const int dz = p >> 2, dy = (p >> 1) & 1, dx = p & 1;
            const int pos = (2 * qz + dz) * 64 + (2 * qy + dy) * 8 + (2 * qx + dx);
            m = fmaxf(m, s_pool[pos * 9 + ch]);
        }
        m = fmaxf(m + s_beta[ch], 0.f);
        const int gz = tz * 4 + qz, gy = ty * 4 + qy, gx = tx * 4 + qx;
        g_h1[(((b * 48 + gz) * 48 + gy) * 48 + gx) * 8 + ch] = m;
    }
}

// ---------------------------------------------------------------------------
// Kernel B (mma.sync tf32, LDS.64 paired): conv2 + BN + ReLU + maxpool2 + FC
// (unchanged from the measured ~73-76us version)
// ---------------------------------------------------------------------------
__global__ void __launch_bounds__(128, 6) conv2_mma_kernel(
    const float* __restrict__ W2,  // [3,3,3,8,16] -> [tap][ci][co]
    const float* __restrict__ b2, const float* __restrict__ g2,
    const float* __restrict__ be2, const float* __restrict__ m2,
    const float* __restrict__ v2,
    const float* __restrict__ Wf,  // [16,5]
    const float* __restrict__ bf,  // [5]
    float* __restrict__ out)       // [8,24,24,24,5]
{
    __shared__ __align__(16) uint32_t s_in[6 * 6 * 80];   // tf32 halo (reused as pool buf)
    __shared__ __align__(16) uint32_t s_wB[27 * 128];     // tf32 weights [tap][co][ci-int]
    __shared__ float s_wf[80], s_beta[16], s_bf[5];

    const int b  = blockIdx.y;
    const int t  = blockIdx.x;                    // 0..863 = 6(x)*12(y)*12(z)
    const int tx = t % 6, ty = (t / 6) % 12, tz = t / 72;
    const int Z0 = tz * 4, Y0 = ty * 4, X0 = tx * 8;
    const int tid = threadIdx.x;
    const int wid = tid >> 5, lane = tid & 31;

    if (tid < 16) {
        float s = g2[tid] * rsqrtf(v2[tid] + BN_EPS);
        s_beta[tid] = (b2[tid] - m2[tid]) * s + be2[tid];
    }
    if (tid < 80) s_wf[tid] = Wf[tid];
    if (tid < 5)  s_bf[tid] = bf[tid];

    // Weights: s_wB[tap*128 + co*8 + slot] ; slot = (ci%4)*2 + ci/4
    for (int i = tid; i < 3456; i += 128) {
        int tap = i >> 7, co = (i >> 3) & 15, slot = i & 7;
        int ci = (slot >> 1) + (slot & 1) * 4;
        float s = g2[co] * rsqrtf(v2[co] + BN_EPS);
        s_wB[i] = f2tf32(W2[tap * 128 + ci * 16 + co] * s);
    }

    // Halo: 360 voxels, tf32 + channel interleave (c0,c4,c1,c5,c2,c6,c3,c7)
    for (int j = tid; j < 360; j += 128) {
        int x10 = j % 10, yz = j / 10;
        int y6 = yz % 6, z6 = yz / 6;
        int gz = Z0 - 1 + z6, gy = Y0 - 1 + y6, gx = X0 - 1 + x10;
        float4 a = make_float4(0.f, 0.f, 0.f, 0.f), c = a;
        if ((unsigned)gz < 48u && (unsigned)gy < 48u && (unsigned)gx < 48u) {
            const float* p = &g_h1[(((b * 48 + gz) * 48 + gy) * 48 + gx) * 8];
            a = *(const float4*)p;
            c = *(const float4*)(p + 4);
        }
        uint32_t* d = &s_in[(z6 * 6 + y6) * 80 + x10 * 8];
        ((uint4*)d)[0] = make_uint4(f2tf32(a.x), f2tf32(c.x), f2tf32(a.y), f2tf32(c.y));
        ((uint4*)d)[1] = make_uint4(f2tf32(a.z), f2tf32(c.z), f2tf32(a.w), f2tf32(c.w));
    }
    __syncthreads();

    const int r_lo = lane >> 2;
    const int ci_lo = lane & 3;
    const int pz = wid;

    const uint2* aBase0 = (const uint2*)&s_in[(pz * 6 + 0) * 80 + r_lo * 8 + 2 * ci_lo];
    const uint2* aBase1 = (const uint2*)&s_in[(pz * 6 + 2) * 80 + r_lo * 8 + 2 * ci_lo];
    const uint2* bBase  = (const uint2*)&s_wB[r_lo * 8 + 2 * ci_lo];

    float d[2][2][4];
    #pragma unroll
    for (int h = 0; h < 2; h++)
        #pragma unroll
        for (int n = 0; n < 2; n++)
            #pragma unroll
            for (int k = 0; k < 4; k++) d[h][n][k] = 0.f;

    #pragma unroll
    for (int tap = 0; tap < 27; tap++) {
        const int dz = tap / 9, dy = (tap / 3) % 3, dx = tap % 3;
        const int aoff = (dz * 480 + dy * 80 + dx * 8) >> 1;
        const uint2 bA = bBase[tap * 64];
        const uint2 bB = bBase[tap * 64 + 32];
        const uint2 l00 = aBase0[aoff];
        const uint2 l01 = aBase0[aoff + 40];
        const uint2 l10 = aBase1[aoff];
        const uint2 l11 = aBase1[aoff + 40];

        mma_tf32_r(d[0][0], l00.x, l01.x, l00.y, l01.y, bA.x, bA.y);
        mma_tf32_r(d[0][1], l00.x, l01.x, l00.y, l01.y, bB.x, bB.y);
        mma_tf32_r(d[1][0], l10.x, l11.x, l10.y, l11.y, bA.x, bA.y);
        mma_tf32_r(d[1][1], l10.x, l11.x, l10.y, l11.y, bB.x, bB.y);
    }

    __syncthreads();
    float* s_pool = (float*)s_in;        // [128 pos][16 co], stride 17
    #pragma unroll
    for (int h = 0; h < 2; h++) {
        const int pos0 = pz * 32 + (h * 2) * 8 + r_lo;
        const int pos1 = pos0 + 8;
        #pragma unroll
        for (int nb = 0; nb < 2; nb++) {
            const int co = nb * 8 + 2 * ci_lo;
            s_pool[pos0 * 17 + co]     = d[h][nb][0];
            s_pool[pos0 * 17 + co + 1] = d[h][nb][1];
            s_pool[pos1 * 17 + co]     = d[h][nb][2];
            s_pool[pos1 * 17 + co + 1] = d[h][nb][3];
        }
    }
    __syncthreads();

    if (tid < 16) {
        const int qx = tid & 3, qy = (tid >> 2) & 1, qz = tid >> 3;
        float mx[16];
        #pragma unroll
        for (int c = 0; c < 16; c++) mx[c] = -3.4e38f;
        #pragma unroll
        for (int p = 0; p < 8; p++) {
            const int ddz = p >> 2, ddy = (p >> 1) & 1, ddx = p & 1;
            const int m = (2 * qz + ddz) * 32 + (2 * qy + ddy) * 8 + (2 * qx + ddx);
            #pragma unroll
            for (int c = 0; c < 16; c++)
                mx[c] = fmaxf(mx[c], s_pool[m * 17 + c]);
        }
        #pragma unroll
        for (int c = 0; c < 16; c++) mx[c] = fmaxf(mx[c] + s_beta[c], 0.f);
        const int gz = tz * 2 + qz, gy = ty * 2 + qy, gx = tx * 4 + qx;
        float* op = &out[(((b * 24 + gz) * 24 + gy) * 24 + gx) * 5];
        #pragma unroll
        for (int n = 0; n < 5; n++) {
            float o = s_bf[n];
            #pragma unroll
            for (int c = 0; c < 16; c++) o += mx[c] * s_wf[c * 5 + n];
            op[n] = o;
        }
    }
}

// ---------------------------------------------------------------------------
extern "C" void kernel_launch(void* const* d_in, const int* in_sizes, int n_in,
                              void* d_out, int out_size) {
    const float* x   = (const float*)d_in[0];
    const float* W1  = (const float*)d_in[1];
    const float* b1  = (const float*)d_in[2];
    const float* g1  = (const float*)d_in[3];
    const float* be1 = (const float*)d_in[4];
    const float* m1  = (const float*)d_in[5];
    const float* v1  = (const float*)d_in[6];
    const float* W2  = (const float*)d_in[7];
    const float* b2  = (const float*)d_in[8];
    const float* g2  = (const float*)d_in[9];
    const float* be2 = (const float*)d_in[10];
    const float* m2  = (const float*)d_in[11];
    const float* v2  = (const float*)d_in[12];
    const float* Wf  = (const float*)d_in[13];
    const float* bf  = (const float*)d_in[14];
    float* out = (float*)d_out;

    dim3 gridA(1728, 8);   // 12x * 12y * 12z conv tiles (8^3 each)
    conv1_mma_kernel<<<gridA, 512>>>(x, W1, b1, g1, be1, m1, v1);

    dim3 gridB(864, 8);
    conv2_mma_kernel<<<gridB, 128>>>(W2, b2, g2, be2, m2, v2, Wf, bf, out);
}

// round 16
// speedup vs baseline: 1.2196x; 1.1805x over previous
#include <cuda_runtime.h>
#include <cuda_bf16.h>
#include <cstdint>

// Intermediate: h1 after conv1+bn+relu+pool : [8,48,48,48,8] floats = 28.3 MB
__device__ float g_h1[8 * 48 * 48 * 48 * 8];
// Pre-folded tf32 conv2 weights [tap][co][ci-interleaved]
__device__ uint32_t g_w2tf[27 * 128];

#define BN_EPS 1e-5f

// ---- packed fp32x2 helpers --------------------------------------------------
__device__ __forceinline__ unsigned long long pk2(float a, float b) {
    unsigned long long r;
    asm("mov.b64 %0, {%1, %2};" : "=l"(r) : "f"(a), "f"(b));
    return r;
}
__device__ __forceinline__ void ffma2(unsigned long long& d,
                                      unsigned long long a,
                                      unsigned long long b) {
    asm("fma.rn.f32x2 %0, %1, %2, %0;" : "+l"(d) : "l"(a), "l"(b));
}
__device__ __forceinline__ float2 upk(unsigned long long v) {
    float2 f;
    asm("mov.b64 {%0, %1}, %2;" : "=f"(f.x), "=f"(f.y) : "l"(v));
    return f;
}

// ---- tf32 mma helpers -------------------------------------------------------
__device__ __forceinline__ uint32_t f2tf32(float f) {
    uint32_t r;
    asm("cvt.rna.tf32.f32 %0, %1;" : "=r"(r) : "f"(f));
    return r;
}
__device__ __forceinline__ void mma_tf32_r(float* d, uint32_t a0, uint32_t a1,
                                           uint32_t a2, uint32_t a3,
                                           uint32_t b0, uint32_t b1) {
    asm volatile(
        "mma.sync.aligned.m16n8k8.row.col.f32.tf32.tf32.f32 "
        "{%0,%1,%2,%3}, {%4,%5,%6,%7}, {%8,%9}, {%0,%1,%2,%3};"
        : "+f"(d[0]), "+f"(d[1]), "+f"(d[2]), "+f"(d[3])
        : "r"(a0), "r"(a1), "r"(a2), "r"(a3), "r"(b0), "r"(b1));
}

// ---------------------------------------------------------------------------
// Prep: fold BN into conv2 weights, tf32-round, interleave. Runs once per
// launch (~2us). g_w2tf[tap*128 + co*8 + slot], slot=(ci%4)*2 + ci/4.
// ---------------------------------------------------------------------------
__global__ void prep_w2_kernel(const float* __restrict__ W2,
                               const float* __restrict__ g2,
                               const float* __restrict__ v2) {
    int i = blockIdx.x * 256 + threadIdx.x;
    if (i < 3456) {
        int tap = i >> 7, co = (i >> 3) & 15, slot = i & 7;
        int ci = (slot >> 1) + (slot & 1) * 4;
        float s = g2[co] * rsqrtf(v2[co] + BN_EPS);
        g_w2tf[i] = f2tf32(W2[tap * 128 + ci * 16 + co] * s);
    }
}

// ---------------------------------------------------------------------------
// Kernel A: conv1 (3x3x3, 1->8) + BN(folded) + ReLU + maxpool2  (FFMA2 path)
// REVERTED to the measured ~89us configuration (R3/R7, 165.1us total).
// ---------------------------------------------------------------------------
__global__ void __launch_bounds__(256, 3) conv1_pool_kernel(
    const float* __restrict__ x,   // [8,96,96,96,1]
    const float* __restrict__ W1,  // [3,3,3,1,8] -> 216
    const float* __restrict__ b1, const float* __restrict__ g1,
    const float* __restrict__ be1, const float* __restrict__ m1,
    const float* __restrict__ v1)
{
    __shared__ float s_in[10 * 208];
    __shared__ __align__(16) float s_w[216];
    __shared__ float s_beta[8];

    const int b  = blockIdx.y;
    const int t  = blockIdx.x;                    // 0..863
    const int tw = t % 6, th = (t / 6) % 12, td = t / 72;
    const int I0z = td * 8 - 1, I0y = th * 8 - 1, I0x = tw * 16 - 1;
    const int tid = threadIdx.x;

    for (int i = tid; i < 1800; i += 256) {
        int z = i / 180, r = i % 180, y = r / 18, w = r % 18;
        int gz = I0z + z, gy = I0y + y, gx = I0x + w;
        float v = 0.f;
        if ((unsigned)gz < 96u && (unsigned)gy < 96u && (unsigned)gx < 96u)
            v = x[((b * 96 + gz) * 96 + gy) * 96 + gx];
        s_in[z * 208 + y * 20 + w] = v;
    }
    if (tid < 216) {
        int c = tid & 7;
        float s = g1[c] * rsqrtf(v1[c] + BN_EPS);
        s_w[tid] = W1[tid] * s;
    }
    if (tid < 8) {
        float s = g1[tid] * rsqrtf(v1[tid] + BN_EPS);
        s_beta[tid] = (b1[tid] - m1[tid]) * s + be1[tid];
    }
    __syncthreads();

    const int dz = tid & 1;
    const int pw = (tid >> 1) & 7, ph = (tid >> 4) & 3, pd = tid >> 6;
    const int cx = 2 * pw, cy = 2 * ph, cz = 2 * pd;

    unsigned long long acc2[4][4];
    #pragma unroll
    for (int p = 0; p < 4; p++)
        #pragma unroll
        for (int c = 0; c < 4; c++) acc2[p][c] = 0ull;

    #pragma unroll 1
    for (int kz = 0; kz < 3; kz++) {
        float xr[4][4];
        const float* sl = &s_in[(cz + dz + kz) * 208 + cy * 20 + cx];
        #pragma unroll
        for (int r = 0; r < 4; r++) {
            float2 a = *(const float2*)(sl + r * 20);
            float2 c = *(const float2*)(sl + r * 20 + 2);
            xr[r][0] = a.x; xr[r][1] = a.y; xr[r][2] = c.x; xr[r][3] = c.y;
        }
        #pragma unroll
        for (int ky = 0; ky < 3; ky++) {
            #pragma unroll
            for (int kx = 0; kx < 3; kx++) {
                const unsigned long long* wp =
                    (const unsigned long long*)&s_w[((kz * 3 + ky) * 3 + kx) * 8];
                const unsigned long long w0 = wp[0], w1 = wp[1],
                                         w2 = wp[2], w3 = wp[3];
                #pragma unroll
                for (int dy = 0; dy < 2; dy++) {
                    #pragma unroll
                    for (int dx = 0; dx < 2; dx++) {
                        const float xv = xr[ky + dy][kx + dx];
                        const unsigned long long xx = pk2(xv, xv);
                        unsigned long long* a = acc2[dy * 2 + dx];
                        ffma2(a[0], xx, w0);
                        ffma2(a[1], xx, w1);
                        ffma2(a[2], xx, w2);
                        ffma2(a[3], xx, w3);
                    }
                }
            }
        }
    }

    float mc[8];
    #pragma unroll
    for (int cp = 0; cp < 4; cp++) {
        float2 f0 = upk(acc2[0][cp]);
        float a = f0.x, c = f0.y;
        #pragma unroll
        for (int p = 1; p < 4; p++) {
            float2 f = upk(acc2[p][cp]);
            a = fmaxf(a, f.x); c = fmaxf(c, f.y);
        }
        mc[2 * cp] = a; mc[2 * cp + 1] = c;
    }
    #pragma unroll
    for (int c = 0; c < 8; c++) {
        mc[c] = fmaxf(mc[c], __shfl_xor_sync(0xFFFFFFFFu, mc[c], 1));
        mc[c] = fmaxf(mc[c] + s_beta[c], 0.f);
    }
    const int gz = td * 4 + pd, gy = th * 4 + ph, gx = tw * 8 + pw;
    float* h1p = &g_h1[(((b * 48 + gz) * 48 + gy) * 48 + gx) * 8 + 4 * dz];
    *(float4*)h1p = make_float4(mc[4 * dz], mc[4 * dz + 1],
                                mc[4 * dz + 2], mc[4 * dz + 3]);
}

// ---------------------------------------------------------------------------
// Kernel B (mma.sync tf32, LDS.64 paired): conv2 + BN + ReLU + maxpool2 + FC
// Changes vs measured 73.3us version: (1) weights copied pre-folded from
// g_w2tf (no per-block refold); (2) parallel epilogue: pool by 128 threads,
// FC by 80 threads.
// ---------------------------------------------------------------------------
__global__ void __launch_bounds__(128, 6) conv2_mma_kernel(
    const float* __restrict__ b2, const float* __restrict__ g2,
    const float* __restrict__ be2, const float* __restrict__ m2,
    const float* __restrict__ v2,
    const float* __restrict__ Wf,  // [16,5]
    const float* __restrict__ bf,  // [5]
    float* __restrict__ out)       // [8,24,24,24,5]
{
    __shared__ __align__(16) uint32_t s_in[6 * 6 * 80];   // tf32 halo (reused as pool buf)
    __shared__ __align__(16) uint32_t s_wB[27 * 128];     // tf32 weights (reused as pooled buf)
    __shared__ float s_wf[80], s_beta[16], s_bf[5];

    const int b  = blockIdx.y;
    const int t  = blockIdx.x;                    // 0..863 = 6(x)*12(y)*12(z)
    const int tx = t % 6, ty = (t / 6) % 12, tz = t / 72;
    const int Z0 = tz * 4, Y0 = ty * 4, X0 = tx * 8;
    const int tid = threadIdx.x;
    const int wid = tid >> 5, lane = tid & 31;

    if (tid < 16) {
        float s = g2[tid] * rsqrtf(v2[tid] + BN_EPS);
        s_beta[tid] = (b2[tid] - m2[tid]) * s + be2[tid];
    }
    if (tid < 80) s_wf[tid] = Wf[tid];
    if (tid < 5)  s_bf[tid] = bf[tid];

    // Weights: straight uint4 copy of pre-folded tf32 (864 uint4)
    for (int i = tid; i < 864; i += 128)
        ((uint4*)s_wB)[i] = ((const uint4*)g_w2tf)[i];

    // Halo: 360 voxels, tf32 + channel interleave (c0,c4,c1,c5,c2,c6,c3,c7)
    for (int j = tid; j < 360; j += 128) {
        int x10 = j % 10, yz = j / 10;
        int y6 = yz % 6, z6 = yz / 6;
        int gz = Z0 - 1 + z6, gy = Y0 - 1 + y6, gx = X0 - 1 + x10;
        float4 a = make_float4(0.f, 0.f, 0.f, 0.f), c = a;
        if ((unsigned)gz < 48u && (unsigned)gy < 48u && (unsigned)gx < 48u) {
            const float* p = &g_h1[(((b * 48 + gz) * 48 + gy) * 48 + gx) * 8];
            a = *(const float4*)p;
            c = *(const float4*)(p + 4);
        }
        uint32_t* d = &s_in[(z6 * 6 + y6) * 80 + x10 * 8];
        ((uint4*)d)[0] = make_uint4(f2tf32(a.x), f2tf32(c.x), f2tf32(a.y), f2tf32(c.y));
        ((uint4*)d)[1] = make_uint4(f2tf32(a.z), f2tf32(c.z), f2tf32(a.w), f2tf32(c.w));
    }
    __syncthreads();

    const int r_lo = lane >> 2;
    const int ci_lo = lane & 3;
    const int pz = wid;

    const uint2* aBase0 = (const uint2*)&s_in[(pz * 6 + 0) * 80 + r_lo * 8 + 2 * ci_lo];
    const uint2* aBase1 = (const uint2*)&s_in[(pz * 6 + 2) * 80 + r_lo * 8 + 2 * ci_lo];
    const uint2* bBase  = (const uint2*)&s_wB[r_lo * 8 + 2 * ci_lo];

    float d[2][2][4];
    #pragma unroll
    for (int h = 0; h < 2; h++)
        #pragma unroll
        for (int n = 0; n < 2; n++)
            #pragma unroll
            for (int k = 0; k < 4; k++) d[h][n][k] = 0.f;

    #pragma unroll
    for (int tap = 0; tap < 27; tap++) {
        const int dz = tap / 9, dy = (tap / 3) % 3, dx = tap % 3;
        const int aoff = (dz * 480 + dy * 80 + dx * 8) >> 1;
        const uint2 bA = bBase[tap * 64];
        const uint2 bB = bBase[tap * 64 + 32];
        const uint2 l00 = aBase0[aoff];
        const uint2 l01 = aBase0[aoff + 40];
        const uint2 l10 = aBase1[aoff];
        const uint2 l11 = aBase1[aoff + 40];

        mma_tf32_r(d[0][0], l00.x, l01.x, l00.y, l01.y, bA.x, bA.y);
        mma_tf32_r(d[0][1], l00.x, l01.x, l00.y, l01.y, bB.x, bB.y);
        mma_tf32_r(d[1][0], l10.x, l11.x, l10.y, l11.y, bA.x, bA.y);
        mma_tf32_r(d[1][1], l10.x, l11.x, l10.y, l11.y, bB.x, bB.y);
    }

    __syncthreads();                     // halo reads done; reuse s_in
    float* s_pool = (float*)s_in;        // [128 pos][16 co], stride 17
    #pragma unroll
    for (int h = 0; h < 2; h++) {
        const int pos0 = pz * 32 + (h * 2) * 8 + r_lo;
        const int pos1 = pos0 + 8;
        #pragma unroll
        for (int nb = 0; nb < 2; nb++) {
            const int co = nb * 8 + 2 * ci_lo;
            s_pool[pos0 * 17 + co]     = d[h][nb][0];
            s_pool[pos0 * 17 + co + 1] = d[h][nb][1];
            s_pool[pos1 * 17 + co]     = d[h][nb][2];
            s_pool[pos1 * 17 + co + 1] = d[h][nb][3];
        }
    }
    __syncthreads();

    // Pool stage: 256 (vox,ch) items over 128 threads (2 each).
    // s_wB is free after the mainloop -> reuse as pooled [16 vox][16 ch].
    float* s_pooled = (float*)s_wB;
    #pragma unroll
    for (int it = 0; it < 2; it++) {
        const int item = tid * 2 + it;          // 0..255
        const int vox = item >> 4, ch = item & 15;
        const int qx = vox & 3, qy = (vox >> 2) & 1, qz = vox >> 3;
        float m = -3.4e38f;
        #pragma unroll
        for (int p = 0; p < 8; p++) {
            const int ddz = p >> 2, ddy = (p >> 1) & 1, ddx = p & 1;
            const int pos = (2 * qz + ddz) * 32 + (2 * qy + ddy) * 8 + (2 * qx + ddx);
            m = fmaxf(m, s_pool[pos * 17 + ch]);
        }
        s_pooled[item] = fmaxf(m + s_beta[ch], 0.f);
    }
    __syncthreads();

    // FC stage: 80 threads, one (vox, n) each
    if (tid < 80) {
        const int vox = tid / 5, n = tid % 5;
        const int qx = vox & 3, qy = (vox >> 2) & 1, qz = vox >> 3;
        float o = s_bf[n];
        #pragma unroll
        for (int c = 0; c < 16; c++) o += s_pooled[vox * 16 + c] * s_wf[c * 5 + n];
        const int gz = tz * 2 + qz, gy = ty * 2 + qy, gx = tx * 4 + qx;
        out[(((b * 24 + gz) * 24 + gy) * 24 + gx) * 5 + n] = o;
    }
}

// ---------------------------------------------------------------------------
extern "C" void kernel_launch(void* const* d_in, const int* in_sizes, int n_in,
                              void* d_out, int out_size) {
    const float* x   = (const float*)d_in[0];
    const float* W1  = (const float*)d_in[1];
    const float* b1  = (const float*)d_in[2];
    const float* g1  = (const float*)d_in[3];
    const float* be1 = (const float*)d_in[4];
    const float* m1  = (const float*)d_in[5];
    const float* v1  = (const float*)d_in[6];
    const float* W2  = (const float*)d_in[7];
    const float* b2  = (const float*)d_in[8];
    const float* g2  = (const float*)d_in[9];
    const float* be2 = (const float*)d_in[10];
    const float* m2  = (const float*)d_in[11];
    const float* v2  = (const float*)d_in[12];
    const float* Wf  = (const float*)d_in[13];
    const float* bf  = (const float*)d_in[14];
    float* out = (float*)d_out;

    prep_w2_kernel<<<14, 256>>>(W2, g2, v2);

    dim3 gridA(864, 8);
    conv1_pool_kernel<<<gridA, 256>>>(x, W1, b1, g1, be1, m1, v1);

    dim3 gridB(864, 8);
    conv2_mma_kernel<<<gridB, 128>>>(b2, g2, be2, m2, v2, Wf, bf, out);
}

// round 17
// speedup vs baseline: 1.2509x; 1.0257x over previous
#include <cuda_runtime.h>
#include <cuda_bf16.h>
#include <cstdint>

// Intermediate: h1 after conv1+bn+relu+pool : [8,48,48,48,8] floats = 28.3 MB
__device__ float g_h1[8 * 48 * 48 * 48 * 8];
// Pre-folded tf32 conv2 weights [tap][co][ci-interleaved]
__device__ uint32_t g_w2tf[27 * 128];

#define BN_EPS 1e-5f

// ---- packed fp32x2 helpers --------------------------------------------------
__device__ __forceinline__ unsigned long long pk2(float a, float b) {
    unsigned long long r;
    asm("mov.b64 %0, {%1, %2};" : "=l"(r) : "f"(a), "f"(b));
    return r;
}
__device__ __forceinline__ void ffma2(unsigned long long& d,
                                      unsigned long long a,
                                      unsigned long long b) {
    asm("fma.rn.f32x2 %0, %1, %2, %0;" : "+l"(d) : "l"(a), "l"(b));
}
__device__ __forceinline__ float2 upk(unsigned long long v) {
    float2 f;
    asm("mov.b64 {%0, %1}, %2;" : "=f"(f.x), "=f"(f.y) : "l"(v));
    return f;
}

// ---- tf32 mma helpers -------------------------------------------------------
__device__ __forceinline__ uint32_t f2tf32(float f) {
    uint32_t r;
    asm("cvt.rna.tf32.f32 %0, %1;" : "=r"(r) : "f"(f));
    return r;
}
__device__ __forceinline__ void mma_tf32_r(float* d, uint32_t a0, uint32_t a1,
                                           uint32_t a2, uint32_t a3,
                                           uint32_t b0, uint32_t b1) {
    asm volatile(
        "mma.sync.aligned.m16n8k8.row.col.f32.tf32.tf32.f32 "
        "{%0,%1,%2,%3}, {%4,%5,%6,%7}, {%8,%9}, {%0,%1,%2,%3};"
        : "+f"(d[0]), "+f"(d[1]), "+f"(d[2]), "+f"(d[3])
        : "r"(a0), "r"(a1), "r"(a2), "r"(a3), "r"(b0), "r"(b1));
}

// ---------------------------------------------------------------------------
// Prep: fold BN into conv2 weights, tf32-round, interleave. Overlapped with
// conv1 on a second stream. g_w2tf[tap*128 + co*8 + slot], slot=(ci%4)*2+ci/4.
// ---------------------------------------------------------------------------
__global__ void prep_w2_kernel(const float* __restrict__ W2,
                               const float* __restrict__ g2,
                               const float* __restrict__ v2) {
    int i = blockIdx.x * 256 + threadIdx.x;
    if (i < 3456) {
        int tap = i >> 7, co = (i >> 3) & 15, slot = i & 7;
        int ci = (slot >> 1) + (slot & 1) * 4;
        float s = g2[co] * rsqrtf(v2[co] + BN_EPS);
        g_w2tf[i] = f2tf32(W2[tap * 128 + ci * 16 + co] * s);
    }
}

// ---------------------------------------------------------------------------
// Kernel A: conv1 (3x3x3, 1->8) + BN(folded) + ReLU + maxpool2  (FFMA2 path)
// Measured ~89us configuration (unchanged).
// ---------------------------------------------------------------------------
__global__ void __launch_bounds__(256, 3) conv1_pool_kernel(
    const float* __restrict__ x,   // [8,96,96,96,1]
    const float* __restrict__ W1,  // [3,3,3,1,8] -> 216
    const float* __restrict__ b1, const float* __restrict__ g1,
    const float* __restrict__ be1, const float* __restrict__ m1,
    const float* __restrict__ v1)
{
    __shared__ float s_in[10 * 208];
    __shared__ __align__(16) float s_w[216];
    __shared__ float s_beta[8];

    const int b  = blockIdx.y;
    const int t  = blockIdx.x;                    // 0..863
    const int tw = t % 6, th = (t / 6) % 12, td = t / 72;
    const int I0z = td * 8 - 1, I0y = th * 8 - 1, I0x = tw * 16 - 1;
    const int tid = threadIdx.x;

    for (int i = tid; i < 1800; i += 256) {
        int z = i / 180, r = i % 180, y = r / 18, w = r % 18;
        int gz = I0z + z, gy = I0y + y, gx = I0x + w;
        float v = 0.f;
        if ((unsigned)gz < 96u && (unsigned)gy < 96u && (unsigned)gx < 96u)
            v = x[((b * 96 + gz) * 96 + gy) * 96 + gx];
        s_in[z * 208 + y * 20 + w] = v;
    }
    if (tid < 216) {
        int c = tid & 7;
        float s = g1[c] * rsqrtf(v1[c] + BN_EPS);
        s_w[tid] = W1[tid] * s;
    }
    if (tid < 8) {
        float s = g1[tid] * rsqrtf(v1[tid] + BN_EPS);
        s_beta[tid] = (b1[tid] - m1[tid]) * s + be1[tid];
    }
    __syncthreads();

    const int dz = tid & 1;
    const int pw = (tid >> 1) & 7, ph = (tid >> 4) & 3, pd = tid >> 6;
    const int cx = 2 * pw, cy = 2 * ph, cz = 2 * pd;

    unsigned long long acc2[4][4];
    #pragma unroll
    for (int p = 0; p < 4; p++)
        #pragma unroll
        for (int c = 0; c < 4; c++) acc2[p][c] = 0ull;

    #pragma unroll 1
    for (int kz = 0; kz < 3; kz++) {
        float xr[4][4];
        const float* sl = &s_in[(cz + dz + kz) * 208 + cy * 20 + cx];
        #pragma unroll
        for (int r = 0; r < 4; r++) {
            float2 a = *(const float2*)(sl + r * 20);
            float2 c = *(const float2*)(sl + r * 20 + 2);
            xr[r][0] = a.x; xr[r][1] = a.y; xr[r][2] = c.x; xr[r][3] = c.y;
        }
        #pragma unroll
        for (int ky = 0; ky < 3; ky++) {
            #pragma unroll
            for (int kx = 0; kx < 3; kx++) {
                const unsigned long long* wp =
                    (const unsigned long long*)&s_w[((kz * 3 + ky) * 3 + kx) * 8];
                const unsigned long long w0 = wp[0], w1 = wp[1],
                                         w2 = wp[2], w3 = wp[3];
                #pragma unroll
                for (int dy = 0; dy < 2; dy++) {
                    #pragma unroll
                    for (int dx = 0; dx < 2; dx++) {
                        const float xv = xr[ky + dy][kx + dx];
                        const unsigned long long xx = pk2(xv, xv);
                        unsigned long long* a = acc2[dy * 2 + dx];
                        ffma2(a[0], xx, w0);
                        ffma2(a[1], xx, w1);
                        ffma2(a[2], xx, w2);
                        ffma2(a[3], xx, w3);
                    }
                }
            }
        }
    }

    float mc[8];
    #pragma unroll
    for (int cp = 0; cp < 4; cp++) {
        float2 f0 = upk(acc2[0][cp]);
        float a = f0.x, c = f0.y;
        #pragma unroll
        for (int p = 1; p < 4; p++) {
            float2 f = upk(acc2[p][cp]);
            a = fmaxf(a, f.x); c = fmaxf(c, f.y);
        }
        mc[2 * cp] = a; mc[2 * cp + 1] = c;
    }
    #pragma unroll
    for (int c = 0; c < 8; c++) {
        mc[c] = fmaxf(mc[c], __shfl_xor_sync(0xFFFFFFFFu, mc[c], 1));
        mc[c] = fmaxf(mc[c] + s_beta[c], 0.f);
    }
    const int gz = td * 4 + pd, gy = th * 4 + ph, gx = tw * 8 + pw;
    float* h1p = &g_h1[(((b * 48 + gz) * 48 + gy) * 48 + gx) * 8 + 4 * dz];
    *(float4*)h1p = make_float4(mc[4 * dz], mc[4 * dz + 1],
                                mc[4 * dz + 2], mc[4 * dz + 3]);
}

// ---------------------------------------------------------------------------
// Kernel B (mma.sync tf32): conv2 + BN + ReLU + maxpool2 + FC
// Doubled tile: 256 threads = 8 warps, 8x x 4y x 8z conv positions, warp=pz.
// Mainloop per warp identical to the measured version (z-stride 480).
// ---------------------------------------------------------------------------
__global__ void __launch_bounds__(256, 3) conv2_mma_kernel(
    const float* __restrict__ b2, const float* __restrict__ g2,
    const float* __restrict__ be2, const float* __restrict__ m2,
    const float* __restrict__ v2,
    const float* __restrict__ Wf,  // [16,5]
    const float* __restrict__ bf,  // [5]
    float* __restrict__ out)       // [8,24,24,24,5]
{
    __shared__ __align__(16) uint32_t s_in[10 * 6 * 80];  // tf32 halo, 19.2 KB (reused as pool buf)
    __shared__ __align__(16) uint32_t s_wB[27 * 128];     // tf32 weights (reused as pooled buf)
    __shared__ float s_wf[80], s_beta[16], s_bf[5];

    const int b  = blockIdx.y;
    const int t  = blockIdx.x;                    // 0..431 = 6(x)*12(y)*6(z)
    const int tx = t % 6, ty = (t / 6) % 12, tz = t / 72;
    const int Z0 = tz * 8, Y0 = ty * 4, X0 = tx * 8;
    const int tid = threadIdx.x;
    const int wid = tid >> 5, lane = tid & 31;

    if (tid < 16) {
        float s = g2[tid] * rsqrtf(v2[tid] + BN_EPS);
        s_beta[tid] = (b2[tid] - m2[tid]) * s + be2[tid];
    }
    if (tid < 80) s_wf[tid] = Wf[tid];
    if (tid < 5)  s_bf[tid] = bf[tid];

    // Weights: straight uint4 copy of pre-folded tf32 (864 uint4)
    for (int i = tid; i < 864; i += 256)
        ((uint4*)s_wB)[i] = ((const uint4*)g_w2tf)[i];

    // Halo: 10z x 6y x 10x voxels, tf32 + channel interleave
    for (int j = tid; j < 600; j += 256) {
        int x10 = j % 10, y6 = (j / 10) % 6, z10 = j / 60;
        int gz = Z0 - 1 + z10, gy = Y0 - 1 + y6, gx = X0 - 1 + x10;
        float4 a = make_float4(0.f, 0.f, 0.f, 0.f), c = a;
        if ((unsigned)gz < 48u && (unsigned)gy < 48u && (unsigned)gx < 48u) {
            const float* p = &g_h1[(((b * 48 + gz) * 48 + gy) * 48 + gx) * 8];
            a = *(const float4*)p;
            c = *(const float4*)(p + 4);
        }
        uint32_t* d = &s_in[(z10 * 6 + y6) * 80 + x10 * 8];
        ((uint4*)d)[0] = make_uint4(f2tf32(a.x), f2tf32(c.x), f2tf32(a.y), f2tf32(c.y));
        ((uint4*)d)[1] = make_uint4(f2tf32(a.z), f2tf32(c.z), f2tf32(a.w), f2tf32(c.w));
    }
    __syncthreads();

    const int r_lo = lane >> 2;
    const int ci_lo = lane & 3;
    const int pz = wid;                           // 0..7

    const uint2* aBase0 = (const uint2*)&s_in[(pz * 6 + 0) * 80 + r_lo * 8 + 2 * ci_lo];
    const uint2* aBase1 = (const uint2*)&s_in[(pz * 6 + 2) * 80 + r_lo * 8 + 2 * ci_lo];
    const uint2* bBase  = (const uint2*)&s_wB[r_lo * 8 + 2 * ci_lo];

    float d[2][2][4];
    #pragma unroll
    for (int h = 0; h < 2; h++)
        #pragma unroll
        for (int n = 0; n < 2; n++)
            #pragma unroll
            for (int k = 0; k < 4; k++) d[h][n][k] = 0.f;

    #pragma unroll
    for (int tap = 0; tap < 27; tap++) {
        const int dz = tap / 9, dy = (tap / 3) % 3, dx = tap % 3;
        const int aoff = (dz * 480 + dy * 80 + dx * 8) >> 1;
        const uint2 bA = bBase[tap * 64];
        const uint2 bB = bBase[tap * 64 + 32];
        const uint2 l00 = aBase0[aoff];
        const uint2 l01 = aBase0[aoff + 40];
        const uint2 l10 = aBase1[aoff];
        const uint2 l11 = aBase1[aoff + 40];

        mma_tf32_r(d[0][0], l00.x, l01.x, l00.y, l01.y, bA.x, bA.y);
        mma_tf32_r(d[0][1], l00.x, l01.x, l00.y, l01.y, bB.x, bB.y);
        mma_tf32_r(d[1][0], l10.x, l11.x, l10.y, l11.y, bA.x, bA.y);
        mma_tf32_r(d[1][1], l10.x, l11.x, l10.y, l11.y, bB.x, bB.y);
    }

    __syncthreads();                     // halo reads done; reuse s_in
    float* s_pool = (float*)s_in;        // [256 pos][16 co], stride 17 (4352 <= 4800)
    #pragma unroll
    for (int h = 0; h < 2; h++) {
        const int pos0 = pz * 32 + (h * 2) * 8 + r_lo;
        const int pos1 = pos0 + 8;
        #pragma unroll
        for (int nb = 0; nb < 2; nb++) {
            const int co = nb * 8 + 2 * ci_lo;
            s_pool[pos0 * 17 + co]     = d[h][nb][0];
            s_pool[pos0 * 17 + co + 1] = d[h][nb][1];
            s_pool[pos1 * 17 + co]     = d[h][nb][2];
            s_pool[pos1 * 17 + co + 1] = d[h][nb][3];
        }
    }
    __syncthreads();

    // Pool stage: 512 (vox,ch) items over 256 threads (2 each).
    // s_wB free after mainloop -> pooled [32 vox][16 ch].
    float* s_pooled = (float*)s_wB;
    #pragma unroll
    for (int it = 0; it < 2; it++) {
        const int item = tid * 2 + it;          // 0..511
        const int vox = item >> 4, ch = item & 15;
        const int qx = vox & 3, qy = (vox >> 2) & 1, qz = vox >> 3;   // qz 0..3
        float m = -3.4e38f;
        #pragma unroll
        for (int p = 0; p < 8; p++) {
            const int ddz = p >> 2, ddy = (p >> 1) & 1, ddx = p & 1;
            const int pos = (2 * qz + ddz) * 32 + (2 * qy + ddy) * 8 + (2 * qx + ddx);
            m = fmaxf(m, s_pool[pos * 17 + ch]);
        }
        s_pooled[item] = fmaxf(m + s_beta[ch], 0.f);
    }
    __syncthreads();

    // FC stage: 160 threads, one (vox, n) each
    if (tid < 160) {
        const int vox = tid / 5, n = tid % 5;
        const int qx = vox & 3, qy = (vox >> 2) & 1, qz = vox >> 3;
        float o = s_bf[n];
        #pragma unroll
        for (int c = 0; c < 16; c++) o += s_pooled[vox * 16 + c] * s_wf[c * 5 + n];
        const int gz = tz * 4 + qz, gy = ty * 2 + qy, gx = tx * 4 + qx;
        out[(((b * 24 + gz) * 24 + gy) * 24 + gx) * 5 + n] = o;
    }
}

// ---------------------------------------------------------------------------
// Launch: prep_w2 forked onto a second stream, overlapping conv1; conv2
// waits on both (fork-join, graph-capturable). Streams/events created once
// on the first (non-captured) correctness call.
// ---------------------------------------------------------------------------
extern "C" void kernel_launch(void* const* d_in, const int* in_sizes, int n_in,
                              void* d_out, int out_size) {
    const float* x   = (const float*)d_in[0];
    const float* W1  = (const float*)d_in[1];
    const float* b1  = (const float*)d_in[2];
    const float* g1  = (const float*)d_in[3];
    const float* be1 = (const float*)d_in[4];
    const float* m1  = (const float*)d_in[5];
    const float* v1  = (const float*)d_in[6];
    const float* W2  = (const float*)d_in[7];
    const float* b2  = (const float*)d_in[8];
    const float* g2  = (const float*)d_in[9];
    const float* be2 = (const float*)d_in[10];
    const float* m2  = (const float*)d_in[11];
    const float* v2  = (const float*)d_in[12];
    const float* Wf  = (const float*)d_in[13];
    const float* bf  = (const float*)d_in[14];
    float* out = (float*)d_out;

    struct Pipe {
        cudaStream_t s2;
        cudaEvent_t evFork, evPrep;
        Pipe() {
            cudaStreamCreateWithFlags(&s2, cudaStreamNonBlocking);
            cudaEventCreateWithFlags(&evFork, cudaEventDisableTiming);
            cudaEventCreateWithFlags(&evPrep, cudaEventDisableTiming);
        }
    };
    static Pipe P;   // first call = correctness run (not captured)

    cudaEventRecord(P.evFork, 0);
    cudaStreamWaitEvent(P.s2, P.evFork, 0);
    prep_w2_kernel<<<14, 256, 0, P.s2>>>(W2, g2, v2);
    cudaEventRecord(P.evPrep, P.s2);

    dim3 gridA(864, 8);
    conv1_pool_kernel<<<gridA, 256>>>(x, W1, b1, g1, be1, m1, v1);

    cudaStreamWaitEvent(0, P.evPrep, 0);
    dim3 gridB(432, 8);
    conv2_mma_kernel<<<gridB, 256>>>(b2, g2, be2, m2, v2, Wf, bf, out);
}